// round 1
// baseline (speedup 1.0000x reference)
#include <cuda_runtime.h>
#include <cuda_bf16.h>
#include <math.h>

// ---------------- problem constants ----------------
#define N_NODES   16384
#define N_EDGES   262144
#define NHID      128
#define NLAYERS   3
#define NBATCH    16
#define NSAMPLES  1024
#define DIMX      4
#define EPSV      1e-5f

// ---------------- device scratch (no allocs allowed) ----------------
__device__ float g_h [N_NODES * NHID];
__device__ float g_Pd[N_NODES * NHID];
__device__ float g_Ps[N_NODES * NHID];
__device__ float g_agg[N_NODES * NHID];
__device__ float g_t1[N_NODES * NHID];
__device__ float g_t2[N_NODES * NHID];
__device__ float g_x [N_NODES * DIMX];
__device__ float g_nstats[2 * NBATCH * NHID];   // [0:2048) sum, [2048:4096) sumsq
__device__ float g_dsum[32];                    // [0:16) sum1, [16:32) sum2

// ---------------- helpers ----------------
__device__ __forceinline__ void red_add_v4(float* p, float a, float b, float c, float d) {
    asm volatile("red.global.add.v4.f32 [%0], {%1,%2,%3,%4};"
                 :: "l"(p), "f"(a), "f"(b), "f"(c), "f"(d) : "memory");
}

__global__ void zero_kernel(float4* __restrict__ p, int n4) {
    int i = blockIdx.x * blockDim.x + threadIdx.x;
    if (i < n4) p[i] = make_float4(0.f, 0.f, 0.f, 0.f);
}

// ---------------- encoder: h = X @ enc_w + enc_b ----------------
__global__ void encoder_kernel(const float* __restrict__ X,
                               const float* __restrict__ W,
                               const float* __restrict__ B,
                               float* __restrict__ H) {
    int idx = blockIdx.x * blockDim.x + threadIdx.x;   // grid covers N_NODES*NHID
    int n = idx >> 7;
    int c = idx & 127;
    float4 xv = ((const float4*)X)[n];
    float v = B[c];
    v += xv.x * W[c];
    v += xv.y * W[128 + c];
    v += xv.z * W[256 + c];
    v += xv.w * W[384 + c];
    H[idx] = v;
}

// ---------------- generic 128-wide GEMM ----------------
// C[M,128] = epi( A[M,KTOT] @ W[KTOT,128] )
// LOADER 0: A = A0 (row stride KTOT)
// LOADER 1: A = concat(A0[M,128], A1[M,128]) along K (KTOT==256)
// LOADER 2: A[e,k] = relu(A0[dst[e],k] + A1[src[e],k] + preBias[k])  (KTOT==128)
// EPI 0: C[m,n] = acc
// EPI 1: C[m,n] = relu(acc + postBias[n])
// EPI 2: red.add C[dst[m], n] += relu(acc + postBias[n])
template<int KTOT, int LOADER, int EPI>
__global__ __launch_bounds__(256)
void gemm128(const float* __restrict__ A0, const float* __restrict__ A1,
             const float* __restrict__ W,  const float* __restrict__ preBias,
             const float* __restrict__ postBias, float* __restrict__ C,
             const int* __restrict__ dstIdx, const int* __restrict__ srcIdx) {
    __shared__ float As[16][128];
    __shared__ float Ws[16][128];

    const int tid  = threadIdx.x;
    const int m0   = blockIdx.x * 128;
    const int arow = tid & 127;
    const int kq   = (tid >> 7) << 3;   // 0 or 8
    const int ty   = tid >> 4;          // 0..15
    const int tx   = tid & 15;          // 0..15
    const int wrow = tid >> 5;          // 0..7
    const int wcol = (tid & 31) << 2;   // 0..124

    const float* pd = nullptr;
    const float* ps = nullptr;
    const float* pa = nullptr;
    if (LOADER == 2) {
        int e = m0 + arow;
        pd = A0 + (size_t)dstIdx[e] * 128 + kq;
        ps = A1 + (size_t)srcIdx[e] * 128 + kq;
    } else if (LOADER == 0) {
        pa = A0 + (size_t)(m0 + arow) * KTOT + kq;
    }

    float acc[8][8];
#pragma unroll
    for (int i = 0; i < 8; ++i)
#pragma unroll
        for (int j = 0; j < 8; ++j) acc[i][j] = 0.f;

    for (int k0 = 0; k0 < KTOT; k0 += 16) {
        // ---- load A tile (transposed into As[k][m]) ----
        float4 t0, t1;
        if (LOADER == 2) {
            float4 x0 = *(const float4*)(pd + k0);
            float4 x1 = *(const float4*)(pd + k0 + 4);
            float4 y0 = *(const float4*)(ps + k0);
            float4 y1 = *(const float4*)(ps + k0 + 4);
            float4 b0 = *(const float4*)(preBias + k0 + kq);
            float4 b1 = *(const float4*)(preBias + k0 + kq + 4);
            t0.x = fmaxf(x0.x + y0.x + b0.x, 0.f);
            t0.y = fmaxf(x0.y + y0.y + b0.y, 0.f);
            t0.z = fmaxf(x0.z + y0.z + b0.z, 0.f);
            t0.w = fmaxf(x0.w + y0.w + b0.w, 0.f);
            t1.x = fmaxf(x1.x + y1.x + b1.x, 0.f);
            t1.y = fmaxf(x1.y + y1.y + b1.y, 0.f);
            t1.z = fmaxf(x1.z + y1.z + b1.z, 0.f);
            t1.w = fmaxf(x1.w + y1.w + b1.w, 0.f);
        } else if (LOADER == 0) {
            t0 = *(const float4*)(pa + k0);
            t1 = *(const float4*)(pa + k0 + 4);
        } else { // concat
            const float* base = (k0 < 128)
                ? (A0 + (size_t)(m0 + arow) * 128 + k0 + kq)
                : (A1 + (size_t)(m0 + arow) * 128 + (k0 - 128) + kq);
            t0 = *(const float4*)(base);
            t1 = *(const float4*)(base + 4);
        }
        As[kq + 0][arow] = t0.x;
        As[kq + 1][arow] = t0.y;
        As[kq + 2][arow] = t0.z;
        As[kq + 3][arow] = t0.w;
        As[kq + 4][arow] = t1.x;
        As[kq + 5][arow] = t1.y;
        As[kq + 6][arow] = t1.z;
        As[kq + 7][arow] = t1.w;

        // ---- load W tile ----
#pragma unroll
        for (int p = 0; p < 2; ++p) {
            int k = wrow + p * 8;
            *(float4*)&Ws[k][wcol] = *(const float4*)(W + (size_t)(k0 + k) * 128 + wcol);
        }
        __syncthreads();

        // ---- compute ----
#pragma unroll
        for (int k = 0; k < 16; ++k) {
            float a[8], w[8];
            *(float4*)&a[0] = *(const float4*)&As[k][ty * 8];
            *(float4*)&a[4] = *(const float4*)&As[k][ty * 8 + 4];
            *(float4*)&w[0] = *(const float4*)&Ws[k][tx * 8];
            *(float4*)&w[4] = *(const float4*)&Ws[k][tx * 8 + 4];
#pragma unroll
            for (int i = 0; i < 8; ++i)
#pragma unroll
                for (int j = 0; j < 8; ++j)
                    acc[i][j] += a[i] * w[j];
        }
        __syncthreads();
    }

    // ---- epilogue ----
    if (EPI == 0) {
#pragma unroll
        for (int i = 0; i < 8; ++i) {
            int m = m0 + ty * 8 + i;
            float* p = C + (size_t)m * 128 + tx * 8;
            *(float4*)(p)     = make_float4(acc[i][0], acc[i][1], acc[i][2], acc[i][3]);
            *(float4*)(p + 4) = make_float4(acc[i][4], acc[i][5], acc[i][6], acc[i][7]);
        }
    } else {
        float4 pb0 = *(const float4*)(postBias + tx * 8);
        float4 pb1 = *(const float4*)(postBias + tx * 8 + 4);
#pragma unroll
        for (int i = 0; i < 8; ++i) {
            int m = m0 + ty * 8 + i;
            float o0 = fmaxf(acc[i][0] + pb0.x, 0.f);
            float o1 = fmaxf(acc[i][1] + pb0.y, 0.f);
            float o2 = fmaxf(acc[i][2] + pb0.z, 0.f);
            float o3 = fmaxf(acc[i][3] + pb0.w, 0.f);
            float o4 = fmaxf(acc[i][4] + pb1.x, 0.f);
            float o5 = fmaxf(acc[i][5] + pb1.y, 0.f);
            float o6 = fmaxf(acc[i][6] + pb1.z, 0.f);
            float o7 = fmaxf(acc[i][7] + pb1.w, 0.f);
            if (EPI == 1) {
                float* p = C + (size_t)m * 128 + tx * 8;
                *(float4*)(p)     = make_float4(o0, o1, o2, o3);
                *(float4*)(p + 4) = make_float4(o4, o5, o6, o7);
            } else {
                int d = dstIdx[m];
                float* p = C + (size_t)d * 128 + tx * 8;
                red_add_v4(p,     o0, o1, o2, o3);
                red_add_v4(p + 4, o4, o5, o6, o7);
            }
        }
    }
}

// ---------------- instance norm ----------------
__global__ void norm_stats_kernel(const float* __restrict__ U) {
    int b = blockIdx.x;        // 0..15
    int ch = blockIdx.y;       // 0..7 node chunks of 128
    int c = threadIdx.x;       // 0..127 channel
    int n0 = b * NSAMPLES + ch * 128;
    float s = 0.f, q = 0.f;
#pragma unroll 4
    for (int i = 0; i < 128; ++i) {
        float v = U[(size_t)(n0 + i) * 128 + c];
        s += v;
        q += v * v;
    }
    atomicAdd(&g_nstats[b * 128 + c], s);
    atomicAdd(&g_nstats[NBATCH * NHID + b * 128 + c], q);
}

__global__ void norm_apply_kernel(const float* __restrict__ U, float* __restrict__ H) {
    int idx = blockIdx.x * blockDim.x + threadIdx.x;
    int n = idx >> 7;
    int c = idx & 127;
    int b = n >> 10;
    float s = g_nstats[b * 128 + c];
    float q = g_nstats[NBATCH * NHID + b * 128 + c];
    float mean = s * (1.0f / NSAMPLES);
    float var = q * (1.0f / NSAMPLES) - mean * mean;
    H[idx] = (U[idx] - mean) * rsqrtf(var + EPSV);
}

// ---------------- decoder: x = sigmoid(h @ dec_w + dec_b) ----------------
__global__ void decoder_kernel(const float* __restrict__ H,
                               const float* __restrict__ W,   // [128,4]
                               const float* __restrict__ B,   // [4]
                               float* __restrict__ GX,
                               float* __restrict__ x_out) {
    int gthread = blockIdx.x * blockDim.x + threadIdx.x;
    int n = gthread >> 5;
    int lane = threadIdx.x & 31;
    if (n >= N_NODES) return;
    const float* hr = H + (size_t)n * 128;
    float a0 = 0.f, a1 = 0.f, a2 = 0.f, a3 = 0.f;
#pragma unroll
    for (int k = 0; k < 128; k += 32) {
        float hv = hr[k + lane];
        float4 w = ((const float4*)W)[k + lane];
        a0 += hv * w.x;
        a1 += hv * w.y;
        a2 += hv * w.z;
        a3 += hv * w.w;
    }
#pragma unroll
    for (int off = 16; off > 0; off >>= 1) {
        a0 += __shfl_xor_sync(0xFFFFFFFFu, a0, off);
        a1 += __shfl_xor_sync(0xFFFFFFFFu, a1, off);
        a2 += __shfl_xor_sync(0xFFFFFFFFu, a2, off);
        a3 += __shfl_xor_sync(0xFFFFFFFFu, a3, off);
    }
    if (lane == 0) {
        float z0 = 1.f / (1.f + expf(-(a0 + B[0])));
        float z1 = 1.f / (1.f + expf(-(a1 + B[1])));
        float z2 = 1.f / (1.f + expf(-(a2 + B[2])));
        float z3 = 1.f / (1.f + expf(-(a3 + B[3])));
        ((float4*)GX)[n] = make_float4(z0, z1, z2, z3);
        if (x_out) {
            x_out[n * 4 + 0] = z0;
            x_out[n * 4 + 1] = z1;
            x_out[n * 4 + 2] = z2;
            x_out[n * 4 + 3] = z3;
        }
    }
}

// ---------------- discrepancy ----------------
__global__ void disc_kernel(const float* __restrict__ GX) {
    __shared__ float4 sx[NSAMPLES];
    __shared__ float red1[128];
    __shared__ float red2[128];
    int b = blockIdx.x;
    int chunk = blockIdx.y;
    int tid = threadIdx.x;
    const float4* xb = (const float4*)GX + (size_t)b * NSAMPLES;
    for (int i = tid; i < NSAMPLES; i += 128) sx[i] = xb[i];
    __syncthreads();
    int i = chunk * 128 + tid;
    float4 xi = sx[i];
    float p1 = (1.f - xi.x * xi.x) * (1.f - xi.y * xi.y) *
               (1.f - xi.z * xi.z) * (1.f - xi.w * xi.w);
    float s2 = 0.f;
#pragma unroll 4
    for (int j = 0; j < NSAMPLES; ++j) {
        float4 xj = sx[j];
        float t = (1.f - fmaxf(xi.x, xj.x)) * (1.f - fmaxf(xi.y, xj.y)) *
                  (1.f - fmaxf(xi.z, xj.z)) * (1.f - fmaxf(xi.w, xj.w));
        s2 += t;
    }
    red1[tid] = p1;
    red2[tid] = s2;
    __syncthreads();
    for (int s = 64; s > 0; s >>= 1) {
        if (tid < s) {
            red1[tid] += red1[tid + s];
            red2[tid] += red2[tid + s];
        }
        __syncthreads();
    }
    if (tid == 0) {
        atomicAdd(&g_dsum[b], red1[0]);
        atomicAdd(&g_dsum[16 + b], red2[0]);
    }
}

__global__ void final_kernel(float* __restrict__ loss_out) {
    if (threadIdx.x == 0 && blockIdx.x == 0) {
        float acc = 0.f;
        const float invN = 1.0f / (float)NSAMPLES;
        for (int b = 0; b < NBATCH; ++b) {
            float s1 = g_dsum[b];
            float s2 = g_dsum[16 + b];
            float v = (1.0f / 81.0f) - invN * 0.125f * s1 + s2 * invN * invN;
            acc += sqrtf(v);
        }
        float loss = acc / (float)NBATCH;
        if (loss_out) *loss_out = loss;
    }
}

// ---------------- launch ----------------
extern "C" void kernel_launch(void* const* d_in, const int* in_sizes, int n_in,
                              void* d_out, int out_size) {
    // resolve input ordering: dict order (setup_inputs) vs reference-signature order
    const float *X, *enc_w, *enc_b, *dec_w, *dec_b;
    const float *m1w, *m1b, *m2w, *m2b, *u1w, *u1b, *u2w, *u2b;
    const int* ei = (const int*)d_in[1];
    X = (const float*)d_in[0];
    bool dictOrder = (in_sizes[5] == 512);   // dec_w in dict order; m1_w otherwise
    if (dictOrder) {
        enc_w = (const float*)d_in[3];  enc_b = (const float*)d_in[4];
        dec_w = (const float*)d_in[5];  dec_b = (const float*)d_in[6];
        m1w = (const float*)d_in[7];    m1b = (const float*)d_in[8];
        m2w = (const float*)d_in[9];    m2b = (const float*)d_in[10];
        u1w = (const float*)d_in[11];   u1b = (const float*)d_in[12];
        u2w = (const float*)d_in[13];   u2b = (const float*)d_in[14];
    } else {
        enc_w = (const float*)d_in[3];  enc_b = (const float*)d_in[4];
        m1w = (const float*)d_in[5];    m1b = (const float*)d_in[6];
        m2w = (const float*)d_in[7];    m2b = (const float*)d_in[8];
        u1w = (const float*)d_in[9];    u1b = (const float*)d_in[10];
        u2w = (const float*)d_in[11];   u2b = (const float*)d_in[12];
        dec_w = (const float*)d_in[13]; dec_b = (const float*)d_in[14];
    }
    const int* src = ei;             // edge_index[0]
    const int* dst = ei + N_EDGES;   // edge_index[1]

    void* p;
    float *h_, *Pd, *Ps, *agg, *t1, *t2, *gx, *nst, *dsum;
    cudaGetSymbolAddress(&p, g_h);      h_  = (float*)p;
    cudaGetSymbolAddress(&p, g_Pd);     Pd  = (float*)p;
    cudaGetSymbolAddress(&p, g_Ps);     Ps  = (float*)p;
    cudaGetSymbolAddress(&p, g_agg);    agg = (float*)p;
    cudaGetSymbolAddress(&p, g_t1);     t1  = (float*)p;
    cudaGetSymbolAddress(&p, g_t2);     t2  = (float*)p;
    cudaGetSymbolAddress(&p, g_x);      gx  = (float*)p;
    cudaGetSymbolAddress(&p, g_nstats); nst = (float*)p;
    cudaGetSymbolAddress(&p, g_dsum);   dsum = (float*)p;

    float* out = (float*)d_out;
    float* loss_out;
    float* x_out;
    if (out_size >= N_NODES * DIMX + 1) { loss_out = out; x_out = out + 1; }
    else if (out_size == N_NODES * DIMX) { loss_out = nullptr; x_out = out; }
    else { loss_out = out; x_out = nullptr; }

    const int NODE_BLOCKS = N_NODES / 128;   // 128
    const int EDGE_BLOCKS = N_EDGES / 128;   // 2048

    encoder_kernel<<<(N_NODES * NHID) / 256, 256>>>(X, enc_w, enc_b, h_);

    for (int l = 0; l < NLAYERS; ++l) {
        const float* W1  = m1w + (size_t)l * 256 * 128;
        const float* B1  = m1b + l * 128;
        const float* W2  = m2w + (size_t)l * 128 * 128;
        const float* B2  = m2b + l * 128;
        const float* WU1 = u1w + (size_t)l * 256 * 128;
        const float* BU1 = u1b + l * 128;
        const float* WU2 = u2w + (size_t)l * 128 * 128;
        const float* BU2 = u2b + l * 128;

        // Pd = h @ W1[:128], Ps = h @ W1[128:]
        gemm128<128, 0, 0><<<NODE_BLOCKS, 256>>>(h_, nullptr, W1, nullptr, nullptr,
                                                 Pd, nullptr, nullptr);
        gemm128<128, 0, 0><<<NODE_BLOCKS, 256>>>(h_, nullptr, W1 + 128 * 128, nullptr, nullptr,
                                                 Ps, nullptr, nullptr);
        // agg = 0
        zero_kernel<<<(N_NODES * NHID / 4) / 256, 256>>>((float4*)agg, N_NODES * NHID / 4);
        // edge MLP + scatter-sum
        gemm128<128, 2, 2><<<EDGE_BLOCKS, 256>>>(Pd, Ps, W2, B1, B2,
                                                 agg, dst, src);
        // u1 = relu(concat(h, agg) @ WU1 + BU1)
        gemm128<256, 1, 1><<<NODE_BLOCKS, 256>>>(h_, agg, WU1, nullptr, BU1,
                                                 t1, nullptr, nullptr);
        // u2 = relu(u1 @ WU2 + BU2)
        gemm128<128, 0, 1><<<NODE_BLOCKS, 256>>>(t1, nullptr, WU2, nullptr, BU2,
                                                 t2, nullptr, nullptr);
        // instance norm -> h
        zero_kernel<<<4, 256>>>((float4*)nst, (2 * NBATCH * NHID) / 4);
        norm_stats_kernel<<<dim3(NBATCH, 8), 128>>>(t2);
        norm_apply_kernel<<<(N_NODES * NHID) / 256, 256>>>(t2, h_);
    }

    decoder_kernel<<<(N_NODES * 32) / 256, 256>>>(h_, dec_w, dec_b, gx, x_out);
    zero_kernel<<<1, 256>>>((float4*)dsum, 8);
    disc_kernel<<<dim3(NBATCH, 8), 128>>>(gx);
    final_kernel<<<1, 1>>>(loss_out);
}

// round 3
// speedup vs baseline: 1.5945x; 1.5945x over previous
#include <cuda_runtime.h>
#include <cuda_bf16.h>
#include <math.h>
#include <stdint.h>

// ---------------- problem constants ----------------
#define N_NODES   16384
#define N_EDGES   262144
#define NHID      128
#define NLAYERS   3
#define NBATCH    16
#define NSAMPLES  1024
#define DIMX      4
#define EPSV      1e-5f

// per-layer prepped weight layout (bytes): W1a 0, W1b 64K, W2 128K, U1 192K(128K), U2 320K
#define WT_LAYER_STRIDE 393216
#define WT_W1A 0
#define WT_W1B 65536
#define WT_W2  131072
#define WT_U1  196608
#define WT_U2  327680

// dynamic smem: 1024 align pad + A hi/lo (64KB) + W hi/lo (64KB)
#define TC_SMEM_DYN 132096

// ---------------- device scratch ----------------
__device__ float g_h [N_NODES * NHID];
__device__ float g_Pd[N_NODES * NHID];
__device__ float g_Ps[N_NODES * NHID];
__device__ float g_agg[N_NODES * NHID];
__device__ float g_t1[N_NODES * NHID];
__device__ float g_t2[N_NODES * NHID];
__device__ float g_x [N_NODES * DIMX];
__device__ float g_nstats[2 * NBATCH * NHID];
__device__ float g_dsum[32];
__device__ char  g_wt[NLAYERS * WT_LAYER_STRIDE];   // prepped bf16 hi/lo swizzled weights

// ---------------- helpers ----------------
__device__ __forceinline__ uint32_t smem_u32(const void* p) {
    uint32_t a;
    asm("{ .reg .u64 t; cvta.to.shared.u64 t, %1; cvt.u32.u64 %0, t; }" : "=r"(a) : "l"(p));
    return a;
}
__device__ __forceinline__ void red_add_v2(float* p, float a, float b) {
    asm volatile("red.global.add.v2.f32 [%0], {%1,%2};"
                 :: "l"(p), "f"(a), "f"(b) : "memory");
}
__device__ __forceinline__ uint32_t pack2(__nv_bfloat16 a, __nv_bfloat16 b) {
    return (uint32_t)__bfloat16_as_ushort(a) | ((uint32_t)__bfloat16_as_ushort(b) << 16);
}
__device__ __forceinline__ void ldmx4(uint32_t* r, uint32_t addr) {
    asm volatile("ldmatrix.sync.aligned.m8n8.x4.shared.b16 {%0,%1,%2,%3}, [%4];"
                 : "=r"(r[0]), "=r"(r[1]), "=r"(r[2]), "=r"(r[3]) : "r"(addr));
}
__device__ __forceinline__ void mma16816(float* c, const uint32_t* a, const uint32_t* b) {
    asm volatile("mma.sync.aligned.m16n8k16.row.col.f32.bf16.bf16.f32 "
                 "{%0,%1,%2,%3}, {%4,%5,%6,%7}, {%8,%9}, {%0,%1,%2,%3};"
                 : "+f"(c[0]), "+f"(c[1]), "+f"(c[2]), "+f"(c[3])
                 : "r"(a[0]), "r"(a[1]), "r"(a[2]), "r"(a[3]), "r"(b[0]), "r"(b[1]));
}

// swizzled byte offset inside a [128 rows][128 bf16] tile.
// row r (256B), col c (bf16): block = c/8 (16B), block' = block ^ (r&7)
__device__ __host__ __forceinline__ uint32_t tile_off(int r, int c) {
    return (uint32_t)(r * 256 + ((((c >> 3) ^ (r & 7)) << 4) | ((c & 7) << 1)));
}

// ---------------- weight prep: fp32 [K,128] -> swizzled bf16 hi/lo [N=128][K] tiles ----------------
struct PrepJobs {
    const float* src[15];
    char* dst[15];
    int nelem[15];
};
__global__ void prep_w_all(PrepJobs jobs) {
    int m = blockIdx.y;
    int idx = blockIdx.x * 256 + threadIdx.x;
    if (idx >= jobs.nelem[m]) return;
    const float* W = jobs.src[m];
    char* out = jobs.dst[m];
    int k = idx >> 7, n = idx & 127;
    float w = W[idx];
    __nv_bfloat16 hi = __float2bfloat16(w);
    __nv_bfloat16 lo = __float2bfloat16(w - __bfloat162float(hi));
    int phase = k >> 7, kk = k & 127;
    uint32_t off = tile_off(n, kk);
    *(__nv_bfloat16*)(out + (size_t)phase * 65536 + off) = hi;
    *(__nv_bfloat16*)(out + (size_t)phase * 65536 + 32768 + off) = lo;
}

// ---------------- HMMA GEMM: C[128,128] tile = epi( A[M,K] @ W[K,128] ) ----------------
// LOADER 0: A row-major fp32 [M,128]                      (NPHASE=1)
// LOADER 1: A = concat(A0,A1) along K (K=256)              (NPHASE=2)
// LOADER 2: A[e,:] = relu(A0[dst[e]] + A1[src[e]] + preBias)  (NPHASE=1)
// EPI 0: store raw; EPI 1: store relu(acc+postBias); EPI 2: red.add C[dst[m]] += relu(acc+postBias)
template<int NPHASE, int LOADER, int EPI>
__global__ __launch_bounds__(512, 1)
void tc_gemm(const float* __restrict__ A0, const float* __restrict__ A1,
             const char* __restrict__ Wt,
             const float* __restrict__ preBias, const float* __restrict__ postBias,
             float* __restrict__ C,
             const int* __restrict__ dstIdx, const int* __restrict__ srcIdx) {
    extern __shared__ char dyn[];
    const int tid = threadIdx.x;
    const int wid = tid >> 5;
    const int lid = tid & 31;
    const int m0  = blockIdx.x * 128;

    uint32_t dyn_u32 = smem_u32(dyn);
    uint32_t pad = ((dyn_u32 + 1023u) & ~1023u) - dyn_u32;
    char* tiles = dyn + pad;
    uint32_t tiles_u32 = dyn_u32 + pad;
    // layout: Ahi @0, Alo @32K, Whi @64K, Wlo @96K

    // staging role
    const int r = tid & 127;
    const int q = tid >> 7;
    const uint32_t r256 = (uint32_t)r * 256;
    const int r7 = r & 7;

    const float* pd = nullptr;
    const float* ps = nullptr;
    if (LOADER == 2) {
        int e = m0 + r;
        pd = A0 + (size_t)dstIdx[e] * 128;
        ps = A1 + (size_t)srcIdx[e] * 128;
    }

    // mma roles
    const int warp_m = wid & 3;        // 4 row groups of 32
    const int warp_n = wid >> 2;       // 4 col groups of 32
    const int quad = lid >> 3;
    const int lrow = lid & 7;
    // A ldmatrix lane mapping: tiles [m0-7|k0-7, m8-15|k0-7, m0-7|k8-15, m8-15|k8-15]
    const int a_rl = (quad & 1) * 8 + lrow;
    const int akq  = quad >> 1;
    uint32_t arow256[2]; int ar7[2];
#pragma unroll
    for (int mt = 0; mt < 2; ++mt) {
        int rr = warp_m * 32 + mt * 16 + a_rl;
        arow256[mt] = (uint32_t)rr * 256; ar7[mt] = rr & 7;
    }
    // B ldmatrix lane mapping: tiles [n(j)|k0-7, n(j)|k8-15, n(j+1)|k0-7, n(j+1)|k8-15]
    const int b_rl = (quad >> 1) * 8 + lrow;
    const int bkq  = quad & 1;
    uint32_t brow256[2]; int br7[2];
#pragma unroll
    for (int pj = 0; pj < 2; ++pj) {
        int rr = warp_n * 32 + pj * 16 + b_rl;
        brow256[pj] = (uint32_t)rr * 256; br7[pj] = rr & 7;
    }

    float c[2][4][4];
#pragma unroll
    for (int mt = 0; mt < 2; ++mt)
#pragma unroll
        for (int nt = 0; nt < 4; ++nt)
#pragma unroll
            for (int i = 0; i < 4; ++i) c[mt][nt][i] = 0.f;

    for (int p = 0; p < NPHASE; ++p) {
        if (p) __syncthreads();
        // ---- stage A: fp32 -> bf16 hi/lo swizzled tiles ----
        {
            const float* Abase = (LOADER == 1 && p == 1) ? A1 : A0;
            char* Ahi = tiles;
            char* Alo = tiles + 32768;
#pragma unroll
            for (int j = 0; j < 8; ++j) {
                int c4 = q * 32 + j * 4;
                float4 v;
                if (LOADER == 2) {
                    float4 a  = *(const float4*)(pd + c4);
                    float4 b  = *(const float4*)(ps + c4);
                    float4 bb = *(const float4*)(preBias + c4);
                    v.x = fmaxf(a.x + b.x + bb.x, 0.f);
                    v.y = fmaxf(a.y + b.y + bb.y, 0.f);
                    v.z = fmaxf(a.z + b.z + bb.z, 0.f);
                    v.w = fmaxf(a.w + b.w + bb.w, 0.f);
                } else {
                    v = *(const float4*)(Abase + (size_t)(m0 + r) * 128 + c4);
                }
                __nv_bfloat16 h0 = __float2bfloat16(v.x);
                __nv_bfloat16 h1 = __float2bfloat16(v.y);
                __nv_bfloat16 h2 = __float2bfloat16(v.z);
                __nv_bfloat16 h3 = __float2bfloat16(v.w);
                __nv_bfloat16 l0 = __float2bfloat16(v.x - __bfloat162float(h0));
                __nv_bfloat16 l1 = __float2bfloat16(v.y - __bfloat162float(h1));
                __nv_bfloat16 l2 = __float2bfloat16(v.z - __bfloat162float(h2));
                __nv_bfloat16 l3 = __float2bfloat16(v.w - __bfloat162float(h3));
                uint32_t off = r256 + ((((c4 >> 3) ^ r7) << 4) | ((c4 & 7) << 1));
                *(uint2*)(Ahi + off) = make_uint2(pack2(h0, h1), pack2(h2, h3));
                *(uint2*)(Alo + off) = make_uint2(pack2(l0, l1), pack2(l2, l3));
            }
        }
        // ---- copy prepped W phase chunk (64KB: hi then lo) ----
        {
            const float4* wsrc = (const float4*)(Wt + (size_t)p * 65536);
            float4* wdst = (float4*)(tiles + 65536);
#pragma unroll
            for (int j = 0; j < 8; ++j)
                wdst[tid + j * 512] = wsrc[tid + j * 512];
        }
        __syncthreads();

        // ---- K loop: 8 steps of k16 ----
#pragma unroll
        for (int ks = 0; ks < 8; ++ks) {
            const int kb = ks * 2;   // 16B-block index of k0
            uint32_t ahi[2][4], alo[2][4], bhi[2][4], blo[2][4];
#pragma unroll
            for (int mt = 0; mt < 2; ++mt) {
                uint32_t sw = (uint32_t)(((kb + akq) ^ ar7[mt]) << 4);
                ldmx4(ahi[mt], tiles_u32 + arow256[mt] + sw);
                ldmx4(alo[mt], tiles_u32 + 32768 + arow256[mt] + sw);
            }
#pragma unroll
            for (int pj = 0; pj < 2; ++pj) {
                uint32_t sw = (uint32_t)(((kb + bkq) ^ br7[pj]) << 4);
                ldmx4(bhi[pj], tiles_u32 + 65536 + brow256[pj] + sw);
                ldmx4(blo[pj], tiles_u32 + 98304 + brow256[pj] + sw);
            }
#pragma unroll
            for (int mt = 0; mt < 2; ++mt)
#pragma unroll
                for (int nt = 0; nt < 4; ++nt) {
                    const uint32_t* bh = &bhi[nt >> 1][(nt & 1) * 2];
                    const uint32_t* bl = &blo[nt >> 1][(nt & 1) * 2];
                    mma16816(c[mt][nt], ahi[mt], bh);
                    mma16816(c[mt][nt], ahi[mt], bl);
                    mma16816(c[mt][nt], alo[mt], bh);
                }
        }
    }

    // ---- epilogue ----
    const int gr = lid >> 2;
    const int gc = (lid & 3) << 1;
#pragma unroll
    for (int mt = 0; mt < 2; ++mt) {
        int mrow = m0 + warp_m * 32 + mt * 16 + gr;
        int d0 = 0, d1 = 0;
        if (EPI == 2) { d0 = dstIdx[mrow]; d1 = dstIdx[mrow + 8]; }
#pragma unroll
        for (int nt = 0; nt < 4; ++nt) {
            int n = warp_n * 32 + nt * 8 + gc;
            float v0 = c[mt][nt][0], v1 = c[mt][nt][1];
            float v2 = c[mt][nt][2], v3 = c[mt][nt][3];
            if (EPI == 0) {
                *(float2*)(C + (size_t)mrow * 128 + n)       = make_float2(v0, v1);
                *(float2*)(C + (size_t)(mrow + 8) * 128 + n) = make_float2(v2, v3);
            } else {
                float2 pb = *(const float2*)(postBias + n);
                float o0 = fmaxf(v0 + pb.x, 0.f);
                float o1 = fmaxf(v1 + pb.y, 0.f);
                float o2 = fmaxf(v2 + pb.x, 0.f);
                float o3 = fmaxf(v3 + pb.y, 0.f);
                if (EPI == 1) {
                    *(float2*)(C + (size_t)mrow * 128 + n)       = make_float2(o0, o1);
                    *(float2*)(C + (size_t)(mrow + 8) * 128 + n) = make_float2(o2, o3);
                } else {
                    if (o0 != 0.f || o1 != 0.f) red_add_v2(C + (size_t)d0 * 128 + n, o0, o1);
                    if (o2 != 0.f || o3 != 0.f) red_add_v2(C + (size_t)d1 * 128 + n, o2, o3);
                }
            }
        }
    }
}

// ---------------- misc kernels ----------------
__global__ void zero_kernel(float4* __restrict__ p, int n4) {
    int i = blockIdx.x * blockDim.x + threadIdx.x;
    if (i < n4) p[i] = make_float4(0.f, 0.f, 0.f, 0.f);
}

__global__ void encoder_kernel(const float* __restrict__ X,
                               const float* __restrict__ W,
                               const float* __restrict__ B,
                               float* __restrict__ H) {
    int idx = blockIdx.x * blockDim.x + threadIdx.x;
    int n = idx >> 7;
    int c = idx & 127;
    float4 xv = ((const float4*)X)[n];
    float v = B[c];
    v += xv.x * W[c];
    v += xv.y * W[128 + c];
    v += xv.z * W[256 + c];
    v += xv.w * W[384 + c];
    H[idx] = v;
}

__global__ void norm_stats_kernel(const float* __restrict__ U) {
    int b = blockIdx.x;
    int ch = blockIdx.y;
    int c = threadIdx.x;
    int n0 = b * NSAMPLES + ch * 128;
    float s = 0.f, qq = 0.f;
#pragma unroll 4
    for (int i = 0; i < 128; ++i) {
        float v = U[(size_t)(n0 + i) * 128 + c];
        s += v;
        qq += v * v;
    }
    atomicAdd(&g_nstats[b * 128 + c], s);
    atomicAdd(&g_nstats[NBATCH * NHID + b * 128 + c], qq);
}

__global__ void norm_apply_kernel(const float* __restrict__ U, float* __restrict__ H) {
    int idx = blockIdx.x * blockDim.x + threadIdx.x;
    int n = idx >> 7;
    int c = idx & 127;
    int b = n >> 10;
    float s = g_nstats[b * 128 + c];
    float qq = g_nstats[NBATCH * NHID + b * 128 + c];
    float mean = s * (1.0f / NSAMPLES);
    float var = qq * (1.0f / NSAMPLES) - mean * mean;
    H[idx] = (U[idx] - mean) * rsqrtf(var + EPSV);
}

__global__ void decoder_kernel(const float* __restrict__ H,
                               const float* __restrict__ W,
                               const float* __restrict__ B,
                               float* __restrict__ GX,
                               float* __restrict__ x_out) {
    int gthread = blockIdx.x * blockDim.x + threadIdx.x;
    int n = gthread >> 5;
    int lane = threadIdx.x & 31;
    if (n >= N_NODES) return;
    const float* hr = H + (size_t)n * 128;
    float a0 = 0.f, a1 = 0.f, a2 = 0.f, a3 = 0.f;
#pragma unroll
    for (int k = 0; k < 128; k += 32) {
        float hv = hr[k + lane];
        float4 w = ((const float4*)W)[k + lane];
        a0 += hv * w.x;
        a1 += hv * w.y;
        a2 += hv * w.z;
        a3 += hv * w.w;
    }
#pragma unroll
    for (int off = 16; off > 0; off >>= 1) {
        a0 += __shfl_xor_sync(0xFFFFFFFFu, a0, off);
        a1 += __shfl_xor_sync(0xFFFFFFFFu, a1, off);
        a2 += __shfl_xor_sync(0xFFFFFFFFu, a2, off);
        a3 += __shfl_xor_sync(0xFFFFFFFFu, a3, off);
    }
    if (lane == 0) {
        float z0 = 1.f / (1.f + expf(-(a0 + B[0])));
        float z1 = 1.f / (1.f + expf(-(a1 + B[1])));
        float z2 = 1.f / (1.f + expf(-(a2 + B[2])));
        float z3 = 1.f / (1.f + expf(-(a3 + B[3])));
        ((float4*)GX)[n] = make_float4(z0, z1, z2, z3);
        if (x_out) {
            x_out[n * 4 + 0] = z0;
            x_out[n * 4 + 1] = z1;
            x_out[n * 4 + 2] = z2;
            x_out[n * 4 + 3] = z3;
        }
    }
}

__global__ void disc_kernel(const float* __restrict__ GX) {
    __shared__ float4 sx[NSAMPLES];
    __shared__ float red1[128];
    __shared__ float red2[128];
    int b = blockIdx.x;
    int chunk = blockIdx.y;
    int tid = threadIdx.x;
    const float4* xb = (const float4*)GX + (size_t)b * NSAMPLES;
    for (int i = tid; i < NSAMPLES; i += 128) sx[i] = xb[i];
    __syncthreads();
    int i = chunk * 128 + tid;
    float4 xi = sx[i];
    float p1 = (1.f - xi.x * xi.x) * (1.f - xi.y * xi.y) *
               (1.f - xi.z * xi.z) * (1.f - xi.w * xi.w);
    float s2 = 0.f;
#pragma unroll 4
    for (int j = 0; j < NSAMPLES; ++j) {
        float4 xj = sx[j];
        float t = (1.f - fmaxf(xi.x, xj.x)) * (1.f - fmaxf(xi.y, xj.y)) *
                  (1.f - fmaxf(xi.z, xj.z)) * (1.f - fmaxf(xi.w, xj.w));
        s2 += t;
    }
    red1[tid] = p1;
    red2[tid] = s2;
    __syncthreads();
    for (int s = 64; s > 0; s >>= 1) {
        if (tid < s) {
            red1[tid] += red1[tid + s];
            red2[tid] += red2[tid + s];
        }
        __syncthreads();
    }
    if (tid == 0) {
        atomicAdd(&g_dsum[b], red1[0]);
        atomicAdd(&g_dsum[16 + b], red2[0]);
    }
}

__global__ void final_kernel(float* __restrict__ loss_out) {
    if (threadIdx.x == 0 && blockIdx.x == 0) {
        float acc = 0.f;
        const float invN = 1.0f / (float)NSAMPLES;
        for (int b = 0; b < NBATCH; ++b) {
            float s1 = g_dsum[b];
            float s2 = g_dsum[16 + b];
            float v = (1.0f / 81.0f) - invN * 0.125f * s1 + s2 * invN * invN;
            acc += sqrtf(v);
        }
        float loss = acc / (float)NBATCH;
        if (loss_out) *loss_out = loss;
    }
}

// ---------------- launch ----------------
extern "C" void kernel_launch(void* const* d_in, const int* in_sizes, int n_in,
                              void* d_out, int out_size) {
    const float *X, *enc_w, *enc_b, *dec_w, *dec_b;
    const float *m1w, *m1b, *m2w, *m2b, *u1w, *u1b, *u2w, *u2b;
    const int* ei = (const int*)d_in[1];
    X = (const float*)d_in[0];
    bool dictOrder = (in_sizes[5] == 512);
    if (dictOrder) {
        enc_w = (const float*)d_in[3];  enc_b = (const float*)d_in[4];
        dec_w = (const float*)d_in[5];  dec_b = (const float*)d_in[6];
        m1w = (const float*)d_in[7];    m1b = (const float*)d_in[8];
        m2w = (const float*)d_in[9];    m2b = (const float*)d_in[10];
        u1w = (const float*)d_in[11];   u1b = (const float*)d_in[12];
        u2w = (const float*)d_in[13];   u2b = (const float*)d_in[14];
    } else {
        enc_w = (const float*)d_in[3];  enc_b = (const float*)d_in[4];
        m1w = (const float*)d_in[5];    m1b = (const float*)d_in[6];
        m2w = (const float*)d_in[7];    m2b = (const float*)d_in[8];
        u1w = (const float*)d_in[9];    u1b = (const float*)d_in[10];
        u2w = (const float*)d_in[11];   u2b = (const float*)d_in[12];
        dec_w = (const float*)d_in[13]; dec_b = (const float*)d_in[14];
    }
    const int* src = ei;
    const int* dst = ei + N_EDGES;

    void* p;
    float *h_, *Pd, *Ps, *agg, *t1, *t2, *gx, *nst, *dsum;
    char* wt;
    cudaGetSymbolAddress(&p, g_h);      h_  = (float*)p;
    cudaGetSymbolAddress(&p, g_Pd);     Pd  = (float*)p;
    cudaGetSymbolAddress(&p, g_Ps);     Ps  = (float*)p;
    cudaGetSymbolAddress(&p, g_agg);    agg = (float*)p;
    cudaGetSymbolAddress(&p, g_t1);     t1  = (float*)p;
    cudaGetSymbolAddress(&p, g_t2);     t2  = (float*)p;
    cudaGetSymbolAddress(&p, g_x);      gx  = (float*)p;
    cudaGetSymbolAddress(&p, g_nstats); nst = (float*)p;
    cudaGetSymbolAddress(&p, g_dsum);   dsum = (float*)p;
    cudaGetSymbolAddress(&p, g_wt);     wt  = (char*)p;

    float* out = (float*)d_out;
    float* loss_out;
    float* x_out;
    if (out_size >= N_NODES * DIMX + 1) { loss_out = out; x_out = out + 1; }
    else if (out_size == N_NODES * DIMX) { loss_out = nullptr; x_out = out; }
    else { loss_out = out; x_out = nullptr; }

    cudaFuncSetAttribute(tc_gemm<1,0,0>, cudaFuncAttributeMaxDynamicSharedMemorySize, TC_SMEM_DYN);
    cudaFuncSetAttribute(tc_gemm<1,0,1>, cudaFuncAttributeMaxDynamicSharedMemorySize, TC_SMEM_DYN);
    cudaFuncSetAttribute(tc_gemm<2,1,1>, cudaFuncAttributeMaxDynamicSharedMemorySize, TC_SMEM_DYN);
    cudaFuncSetAttribute(tc_gemm<1,2,2>, cudaFuncAttributeMaxDynamicSharedMemorySize, TC_SMEM_DYN);

    // ---- weight prep (15 jobs: 5 matrices x 3 layers) ----
    PrepJobs jobs;
    for (int l = 0; l < NLAYERS; ++l) {
        char* lb = wt + (size_t)l * WT_LAYER_STRIDE;
        jobs.src[l*5+0] = m1w + (size_t)l * 256 * 128;            jobs.dst[l*5+0] = lb + WT_W1A; jobs.nelem[l*5+0] = 128*128;
        jobs.src[l*5+1] = m1w + (size_t)l * 256 * 128 + 128*128;  jobs.dst[l*5+1] = lb + WT_W1B; jobs.nelem[l*5+1] = 128*128;
        jobs.src[l*5+2] = m2w + (size_t)l * 128 * 128;            jobs.dst[l*5+2] = lb + WT_W2;  jobs.nelem[l*5+2] = 128*128;
        jobs.src[l*5+3] = u1w + (size_t)l * 256 * 128;            jobs.dst[l*5+3] = lb + WT_U1;  jobs.nelem[l*5+3] = 256*128;
        jobs.src[l*5+4] = u2w + (size_t)l * 128 * 128;            jobs.dst[l*5+4] = lb + WT_U2;  jobs.nelem[l*5+4] = 128*128;
    }
    prep_w_all<<<dim3(128, 15), 256>>>(jobs);

    const int NODE_BLOCKS = N_NODES / 128;   // 128
    const int EDGE_BLOCKS = N_EDGES / 128;   // 2048

    encoder_kernel<<<(N_NODES * NHID) / 256, 256>>>(X, enc_w, enc_b, h_);

    for (int l = 0; l < NLAYERS; ++l) {
        char* lb = wt + (size_t)l * WT_LAYER_STRIDE;
        const float* B1  = m1b + l * 128;
        const float* B2  = m2b + l * 128;
        const float* BU1 = u1b + l * 128;
        const float* BU2 = u2b + l * 128;

        tc_gemm<1,0,0><<<NODE_BLOCKS, 512, TC_SMEM_DYN>>>(h_, nullptr, lb + WT_W1A,
                                                          nullptr, nullptr, Pd, nullptr, nullptr);
        tc_gemm<1,0,0><<<NODE_BLOCKS, 512, TC_SMEM_DYN>>>(h_, nullptr, lb + WT_W1B,
                                                          nullptr, nullptr, Ps, nullptr, nullptr);
        zero_kernel<<<(N_NODES * NHID / 4) / 256, 256>>>((float4*)agg, N_NODES * NHID / 4);
        tc_gemm<1,2,2><<<EDGE_BLOCKS, 512, TC_SMEM_DYN>>>(Pd, Ps, lb + WT_W2,
                                                          B1, B2, agg, dst, src);
        tc_gemm<2,1,1><<<NODE_BLOCKS, 512, TC_SMEM_DYN>>>(h_, agg, lb + WT_U1,
                                                          nullptr, BU1, t1, nullptr, nullptr);
        tc_gemm<1,0,1><<<NODE_BLOCKS, 512, TC_SMEM_DYN>>>(t1, nullptr, lb + WT_U2,
                                                          nullptr, BU2, t2, nullptr, nullptr);
        zero_kernel<<<4, 256>>>((float4*)nst, (2 * NBATCH * NHID) / 4);
        norm_stats_kernel<<<dim3(NBATCH, 8), 128>>>(t2);
        norm_apply_kernel<<<(N_NODES * NHID) / 256, 256>>>(t2, h_);
    }

    decoder_kernel<<<(N_NODES * 32) / 256, 256>>>(h_, dec_w, dec_b, gx, x_out);
    zero_kernel<<<1, 256>>>((float4*)dsum, 8);
    disc_kernel<<<dim3(NBATCH, 8), 128>>>(gx);
    final_kernel<<<1, 1>>>(loss_out);
}

// round 4
// speedup vs baseline: 1.8985x; 1.1906x over previous
#include <cuda_runtime.h>
#include <cuda_bf16.h>
#include <math.h>
#include <stdint.h>

// ---------------- problem constants ----------------
#define N_NODES   16384
#define N_EDGES   262144
#define NHID      128
#define NLAYERS   3
#define NBATCH    16
#define NSAMPLES  1024
#define DIMX      4
#define EPSV      1e-5f

#define WT_LAYER_STRIDE 393216
#define WT_W1A 0
#define WT_W1B 65536
#define WT_W2  131072
#define WT_U1  196608
#define WT_U2  327680

#define NODE_SMEM  99328    // 1K pad + A hi/lo 32K + W hi/lo 64K
#define EDGE_SMEM  197632   // 1K pad + 2 A bufs (2*64K) + W 64K
#define U1_SMEM    132096   // 1K pad + A 64K + W 64K

// ---------------- device scratch ----------------
__device__ float g_h [N_NODES * NHID];
__device__ float g_Pd[N_NODES * NHID];
__device__ float g_Ps[N_NODES * NHID];
__device__ float g_agg[N_NODES * NHID];
__device__ float g_t1[N_NODES * NHID];
__device__ float g_t2[N_NODES * NHID];
__device__ float g_x [N_NODES * DIMX];
__device__ float g_nstats[2 * NBATCH * NHID];   // [0:2048) mean/sum, [2048:4096) invstd/sumsq
__device__ float g_dsum[32];
__device__ char  g_wt[NLAYERS * WT_LAYER_STRIDE];

// ---------------- helpers ----------------
__device__ __forceinline__ uint32_t smem_u32(const void* p) {
    uint32_t a;
    asm("{ .reg .u64 t; cvta.to.shared.u64 t, %1; cvt.u32.u64 %0, t; }" : "=r"(a) : "l"(p));
    return a;
}
__device__ __forceinline__ void red_add_v2(float* p, float a, float b) {
    asm volatile("red.global.add.v2.f32 [%0], {%1,%2};"
                 :: "l"(p), "f"(a), "f"(b) : "memory");
}
__device__ __forceinline__ uint32_t pack2(__nv_bfloat16 a, __nv_bfloat16 b) {
    return (uint32_t)__bfloat16_as_ushort(a) | ((uint32_t)__bfloat16_as_ushort(b) << 16);
}
__device__ __forceinline__ void ldmx4(uint32_t* r, uint32_t addr) {
    asm volatile("ldmatrix.sync.aligned.m8n8.x4.shared.b16 {%0,%1,%2,%3}, [%4];"
                 : "=r"(r[0]), "=r"(r[1]), "=r"(r[2]), "=r"(r[3]) : "r"(addr));
}
__device__ __forceinline__ void mma16816(float* c, const uint32_t* a, const uint32_t* b) {
    asm volatile("mma.sync.aligned.m16n8k16.row.col.f32.bf16.bf16.f32 "
                 "{%0,%1,%2,%3}, {%4,%5,%6,%7}, {%8,%9}, {%0,%1,%2,%3};"
                 : "+f"(c[0]), "+f"(c[1]), "+f"(c[2]), "+f"(c[3])
                 : "r"(a[0]), "r"(a[1]), "r"(a[2]), "r"(a[3]), "r"(b[0]), "r"(b[1]));
}
#define BAR_SYNC(id)   asm volatile("bar.sync %0, 512;"   :: "r"(id) : "memory")
#define BAR_ARRIVE(id) asm volatile("bar.arrive %0, 512;" :: "r"(id) : "memory")

// split fp32 float4 into bf16 hi/lo packed uint2 pairs
__device__ __forceinline__ void split4(float4 v, uint2& hv, uint2& lv) {
    __nv_bfloat16 h0 = __float2bfloat16(v.x);
    __nv_bfloat16 h1 = __float2bfloat16(v.y);
    __nv_bfloat16 h2 = __float2bfloat16(v.z);
    __nv_bfloat16 h3 = __float2bfloat16(v.w);
    __nv_bfloat16 l0 = __float2bfloat16(v.x - __bfloat162float(h0));
    __nv_bfloat16 l1 = __float2bfloat16(v.y - __bfloat162float(h1));
    __nv_bfloat16 l2 = __float2bfloat16(v.z - __bfloat162float(h2));
    __nv_bfloat16 l3 = __float2bfloat16(v.w - __bfloat162float(h3));
    hv = make_uint2(pack2(h0, h1), pack2(h2, h3));
    lv = make_uint2(pack2(l0, l1), pack2(l2, l3));
}

// ---------------- weight prep: fp32 [K,128] -> swizzled bf16 hi/lo [N=128][K] tiles ----------------
struct PrepJobs {
    const float* src[15];
    char* dst[15];
    int nelem[15];
};
__global__ void prep_w_all(PrepJobs jobs) {
    int m = blockIdx.y;
    int idx = blockIdx.x * 256 + threadIdx.x;
    if (idx >= jobs.nelem[m]) return;
    const float* W = jobs.src[m];
    char* out = jobs.dst[m];
    int k = idx >> 7, n = idx & 127;
    float w = W[idx];
    __nv_bfloat16 hi = __float2bfloat16(w);
    __nv_bfloat16 lo = __float2bfloat16(w - __bfloat162float(hi));
    int phase = k >> 7, kk = k & 127;
    uint32_t off = (uint32_t)(n * 256 + ((((kk >> 3) ^ (n & 7)) << 4) | ((kk & 7) << 1)));
    *(__nv_bfloat16*)(out + (size_t)phase * 65536 + off) = hi;
    *(__nv_bfloat16*)(out + (size_t)phase * 65536 + 32768 + off) = lo;
}

// ---------------- node GEMM: 64-row tiles, 256 threads, 2 CTAs/SM ----------------
// DUAL: blockIdx>>8 selects W half (+64KB) and C0/C1.  EPI 0: raw; EPI 1: relu+bias.
// NORM: A = (A0 - mean)*invstd per (batch, col) from nstats.
template<int DUAL, int EPI, int NORM>
__global__ __launch_bounds__(256, 2)
void tc_node(const float* __restrict__ A0, const char* __restrict__ Wt,
             const float* __restrict__ postBias,
             float* __restrict__ C0, float* __restrict__ C1,
             const float* __restrict__ nstats) {
    extern __shared__ char dyn[];
    const int tid = threadIdx.x;
    const int wid = tid >> 5;
    const int lid = tid & 31;
    uint32_t dyn_u32 = smem_u32(dyn);
    uint32_t pad = ((dyn_u32 + 1023u) & ~1023u) - dyn_u32;
    char* tiles = dyn + pad;
    uint32_t tiles_u32 = dyn_u32 + pad;
    // Ahi @0 (16K), Alo @16K, Whi @32K, Wlo @64K

    const int half  = DUAL ? (blockIdx.x >> 8) : 0;
    const int tileI = DUAL ? (blockIdx.x & 255) : blockIdx.x;
    const char* W = Wt + half * 65536;
    float* C = (DUAL && half) ? C1 : C0;
    const int m0 = tileI * 64;

    // ---- stage A ----
    {
        const int r  = tid & 63;
        const int q  = tid >> 6;
        const int r7 = r & 7;
        const uint32_t r256 = (uint32_t)r * 256;
        const int node = m0 + r;
        const float* arow = A0 + (size_t)node * 128;
        const float* nm = NORM ? (nstats + (node >> 10) * 128) : nullptr;
#pragma unroll
        for (int j = 0; j < 8; ++j) {
            int c4 = q * 32 + j * 4;
            float4 v = *(const float4*)(arow + c4);
            if (NORM) {
                float4 m  = *(const float4*)(nm + c4);
                float4 iv = *(const float4*)(nm + 2048 + c4);
                v.x = (v.x - m.x) * iv.x;
                v.y = (v.y - m.y) * iv.y;
                v.z = (v.z - m.z) * iv.z;
                v.w = (v.w - m.w) * iv.w;
            }
            uint2 hv, lv;
            split4(v, hv, lv);
            uint32_t off = r256 + ((((c4 >> 3) ^ r7) << 4) | ((c4 & 7) << 1));
            *(uint2*)(tiles + off) = hv;
            *(uint2*)(tiles + 16384 + off) = lv;
        }
    }
    // ---- copy W (64KB) ----
    {
        const float4* wsrc = (const float4*)W;
        float4* wdst = (float4*)(tiles + 32768);
#pragma unroll
        for (int j = 0; j < 16; ++j)
            wdst[tid + j * 256] = wsrc[tid + j * 256];
    }
    __syncthreads();

    // ---- compute: warp = 16 rows x 64 cols ----
    const int warp_m = wid & 3;
    const int warp_n = wid >> 2;
    const int quad = lid >> 3;
    const int lrow = lid & 7;
    const int a_rl = (quad & 1) * 8 + lrow;
    const int akq  = quad >> 1;
    const int b_rl = (quad >> 1) * 8 + lrow;
    const int bkq  = quad & 1;
    const int arr = warp_m * 16 + a_rl;
    const uint32_t arow256 = (uint32_t)arr * 256;
    const int ar7v = arr & 7;
    uint32_t brow256[4]; int br7[4];
#pragma unroll
    for (int pj = 0; pj < 4; ++pj) {
        int rr = warp_n * 64 + pj * 16 + b_rl;
        brow256[pj] = (uint32_t)rr * 256; br7[pj] = rr & 7;
    }

    float c[8][4];
#pragma unroll
    for (int nt = 0; nt < 8; ++nt)
#pragma unroll
        for (int i = 0; i < 4; ++i) c[nt][i] = 0.f;

#pragma unroll
    for (int ks = 0; ks < 8; ++ks) {
        const int kb = ks * 2;
        uint32_t ahi[4], alo[4];
        uint32_t sw = (uint32_t)(((kb + akq) ^ ar7v) << 4);
        ldmx4(ahi, tiles_u32 + arow256 + sw);
        ldmx4(alo, tiles_u32 + 16384 + arow256 + sw);
#pragma unroll
        for (int pj = 0; pj < 4; ++pj) {
            uint32_t bh[4], bl[4];
            uint32_t swb = (uint32_t)(((kb + bkq) ^ br7[pj]) << 4);
            ldmx4(bh, tiles_u32 + 32768 + brow256[pj] + swb);
            ldmx4(bl, tiles_u32 + 65536 + brow256[pj] + swb);
#pragma unroll
            for (int sub = 0; sub < 2; ++sub) {
                float* cc = c[pj * 2 + sub];
                mma16816(cc, ahi, bh + sub * 2);
                mma16816(cc, ahi, bl + sub * 2);
                mma16816(cc, alo, bh + sub * 2);
            }
        }
    }

    // ---- epilogue ----
    const int gr = lid >> 2;
    const int gc = (lid & 3) << 1;
    const int mrow = m0 + warp_m * 16 + gr;
#pragma unroll
    for (int nt = 0; nt < 8; ++nt) {
        int n = warp_n * 64 + nt * 8 + gc;
        float v0 = c[nt][0], v1 = c[nt][1], v2 = c[nt][2], v3 = c[nt][3];
        if (EPI == 0) {
            *(float2*)(C + (size_t)mrow * 128 + n)       = make_float2(v0, v1);
            *(float2*)(C + (size_t)(mrow + 8) * 128 + n) = make_float2(v2, v3);
        } else {
            float2 pb = *(const float2*)(postBias + n);
            *(float2*)(C + (size_t)mrow * 128 + n) =
                make_float2(fmaxf(v0 + pb.x, 0.f), fmaxf(v1 + pb.y, 0.f));
            *(float2*)(C + (size_t)(mrow + 8) * 128 + n) =
                make_float2(fmaxf(v2 + pb.x, 0.f), fmaxf(v3 + pb.y, 0.f));
        }
    }
}

// ---------------- edge GEMM: persistent, warp-specialized ----------------
// warps 8-15 producers: gather relu(Pd[dst]+Ps[src]+B1), split, store to A buf
// warps 0-7 consumers:  MMA vs resident W, epilogue red.add agg[dst] += relu(acc+B2)
__global__ __launch_bounds__(512, 1)
void tc_edge(const float* __restrict__ Pd, const float* __restrict__ Ps,
             const char* __restrict__ Wt,
             const float* __restrict__ preBias, const float* __restrict__ postBias,
             float* __restrict__ C,
             const int* __restrict__ dstIdx, const int* __restrict__ srcIdx) {
    extern __shared__ char dyn[];
    const int tid = threadIdx.x;
    const int wid = tid >> 5;
    const int lid = tid & 31;
    uint32_t dyn_u32 = smem_u32(dyn);
    uint32_t pad = ((dyn_u32 + 1023u) & ~1023u) - dyn_u32;
    char* tiles = dyn + pad;
    uint32_t tiles_u32 = dyn_u32 + pad;
    // buf0 @0 (hi 32K, lo @32K), buf1 @64K, W @128K (hi, lo @+32K)

    // all 512 threads: copy W once
    {
        const float4* wsrc = (const float4*)Wt;
        float4* wdst = (float4*)(tiles + 131072);
#pragma unroll
        for (int j = 0; j < 8; ++j)
            wdst[tid + j * 512] = wsrc[tid + j * 512];
    }
    __syncthreads();

    const int grid = gridDim.x;
    const int NT = N_EDGES / 128;

    if (wid >= 8) {
        // ---------------- producer ----------------
        const int ptid = tid - 256;
        const int r  = ptid & 127;
        const int q2 = ptid >> 7;
        const int r7 = r & 7;
        const uint32_t r256 = (uint32_t)r * 256;
        int i = 0;
        for (int tile = blockIdx.x; tile < NT; tile += grid, ++i) {
            int b = i & 1;
            if (i >= 2) BAR_SYNC(3 + b);
            int e = tile * 128 + r;
            const float* pd = Pd + (size_t)dstIdx[e] * 128;
            const float* ps = Ps + (size_t)srcIdx[e] * 128;
            char* Ah = tiles + b * 65536;
            char* Al = Ah + 32768;
#pragma unroll 4
            for (int j = 0; j < 16; ++j) {
                int c4 = q2 * 64 + j * 4;
                float4 a  = *(const float4*)(pd + c4);
                float4 s  = *(const float4*)(ps + c4);
                float4 bb = *(const float4*)(preBias + c4);
                float4 v;
                v.x = fmaxf(a.x + s.x + bb.x, 0.f);
                v.y = fmaxf(a.y + s.y + bb.y, 0.f);
                v.z = fmaxf(a.z + s.z + bb.z, 0.f);
                v.w = fmaxf(a.w + s.w + bb.w, 0.f);
                uint2 hv, lv;
                split4(v, hv, lv);
                uint32_t off = r256 + ((((c4 >> 3) ^ r7) << 4) | ((c4 & 7) << 1));
                *(uint2*)(Ah + off) = hv;
                *(uint2*)(Al + off) = lv;
            }
            __threadfence_block();
            BAR_ARRIVE(1 + b);
        }
    } else {
        // ---------------- consumer ----------------
        const int warp_m = wid & 3;
        const int warp_n = wid >> 2;   // 0..1
        const int quad = lid >> 3;
        const int lrow = lid & 7;
        const int a_rl = (quad & 1) * 8 + lrow;
        const int akq  = quad >> 1;
        const int b_rl = (quad >> 1) * 8 + lrow;
        const int bkq  = quad & 1;
        uint32_t arow256[2]; int ar7[2];
#pragma unroll
        for (int mt = 0; mt < 2; ++mt) {
            int rr = warp_m * 32 + mt * 16 + a_rl;
            arow256[mt] = (uint32_t)rr * 256; ar7[mt] = rr & 7;
        }
        uint32_t brow256[4]; int br7[4];
#pragma unroll
        for (int pj = 0; pj < 4; ++pj) {
            int rr = warp_n * 64 + pj * 16 + b_rl;
            brow256[pj] = (uint32_t)rr * 256; br7[pj] = rr & 7;
        }
        const int gr = lid >> 2;
        const int gc = (lid & 3) << 1;

        int i = 0;
        for (int tile = blockIdx.x; tile < NT; tile += grid, ++i) {
            int b = i & 1;
            BAR_SYNC(1 + b);
            uint32_t Abase = tiles_u32 + b * 65536;

            float c[2][8][4];
#pragma unroll
            for (int mt = 0; mt < 2; ++mt)
#pragma unroll
                for (int nt = 0; nt < 8; ++nt)
#pragma unroll
                    for (int k = 0; k < 4; ++k) c[mt][nt][k] = 0.f;

#pragma unroll
            for (int ks = 0; ks < 8; ++ks) {
                const int kb = ks * 2;
                uint32_t ahi[2][4], alo[2][4];
#pragma unroll
                for (int mt = 0; mt < 2; ++mt) {
                    uint32_t sw = (uint32_t)(((kb + akq) ^ ar7[mt]) << 4);
                    ldmx4(ahi[mt], Abase + arow256[mt] + sw);
                    ldmx4(alo[mt], Abase + 32768 + arow256[mt] + sw);
                }
#pragma unroll
                for (int pj = 0; pj < 4; ++pj) {
                    uint32_t bh[4], bl[4];
                    uint32_t swb = (uint32_t)(((kb + bkq) ^ br7[pj]) << 4);
                    ldmx4(bh, tiles_u32 + 131072 + brow256[pj] + swb);
                    ldmx4(bl, tiles_u32 + 163840 + brow256[pj] + swb);
#pragma unroll
                    for (int mt = 0; mt < 2; ++mt)
#pragma unroll
                        for (int sub = 0; sub < 2; ++sub) {
                            float* cc = c[mt][pj * 2 + sub];
                            mma16816(cc, ahi[mt], bh + sub * 2);
                            mma16816(cc, ahi[mt], bl + sub * 2);
                            mma16816(cc, alo[mt], bh + sub * 2);
                        }
                }
            }
            BAR_ARRIVE(3 + b);   // buffer free; producer can refill while we do atomics

            // epilogue: scatter-add
#pragma unroll
            for (int mt = 0; mt < 2; ++mt) {
                int mrow = tile * 128 + warp_m * 32 + mt * 16 + gr;
                int d0 = dstIdx[mrow];
                int d1 = dstIdx[mrow + 8];
#pragma unroll
                for (int nt = 0; nt < 8; ++nt) {
                    int n = warp_n * 64 + nt * 8 + gc;
                    float2 pb = *(const float2*)(postBias + n);
                    float o0 = fmaxf(c[mt][nt][0] + pb.x, 0.f);
                    float o1 = fmaxf(c[mt][nt][1] + pb.y, 0.f);
                    float o2 = fmaxf(c[mt][nt][2] + pb.x, 0.f);
                    float o3 = fmaxf(c[mt][nt][3] + pb.y, 0.f);
                    if (o0 != 0.f || o1 != 0.f) red_add_v2(C + (size_t)d0 * 128 + n, o0, o1);
                    if (o2 != 0.f || o3 != 0.f) red_add_v2(C + (size_t)d1 * 128 + n, o2, o3);
                }
            }
        }
    }
}

// ---------------- U1 GEMM (concat h|agg, K=256): 512 threads, 128-row tile ----------------
template<int NORM>
__global__ __launch_bounds__(512, 1)
void tc_u1(const float* __restrict__ A0, const float* __restrict__ A1,
           const char* __restrict__ Wt, const float* __restrict__ postBias,
           float* __restrict__ C, const float* __restrict__ nstats) {
    extern __shared__ char dyn[];
    const int tid = threadIdx.x;
    const int wid = tid >> 5;
    const int lid = tid & 31;
    const int m0  = blockIdx.x * 128;
    uint32_t dyn_u32 = smem_u32(dyn);
    uint32_t pad = ((dyn_u32 + 1023u) & ~1023u) - dyn_u32;
    char* tiles = dyn + pad;
    uint32_t tiles_u32 = dyn_u32 + pad;
    // Ahi @0, Alo @32K, Whi @64K, Wlo @96K

    const int r  = tid & 127;
    const int q  = tid >> 7;
    const uint32_t r256 = (uint32_t)r * 256;
    const int r7 = r & 7;

    const int warp_m = wid & 3;
    const int warp_n = wid >> 2;
    const int quad = lid >> 3;
    const int lrow = lid & 7;
    const int a_rl = (quad & 1) * 8 + lrow;
    const int akq  = quad >> 1;
    const int b_rl = (quad >> 1) * 8 + lrow;
    const int bkq  = quad & 1;
    uint32_t arow256[2]; int ar7[2];
#pragma unroll
    for (int mt = 0; mt < 2; ++mt) {
        int rr = warp_m * 32 + mt * 16 + a_rl;
        arow256[mt] = (uint32_t)rr * 256; ar7[mt] = rr & 7;
    }
    uint32_t brow256[2]; int br7[2];
#pragma unroll
    for (int pj = 0; pj < 2; ++pj) {
        int rr = warp_n * 32 + pj * 16 + b_rl;
        brow256[pj] = (uint32_t)rr * 256; br7[pj] = rr & 7;
    }

    float c[2][4][4];
#pragma unroll
    for (int mt = 0; mt < 2; ++mt)
#pragma unroll
        for (int nt = 0; nt < 4; ++nt)
#pragma unroll
            for (int i = 0; i < 4; ++i) c[mt][nt][i] = 0.f;

    for (int p = 0; p < 2; ++p) {
        if (p) __syncthreads();
        // stage A phase p
        {
            const float* Abase = p ? A1 : A0;
            const int node = m0 + r;
            const float* arow = Abase + (size_t)node * 128;
            const float* nm = (NORM && p == 0) ? (nstats + (node >> 10) * 128) : nullptr;
#pragma unroll
            for (int j = 0; j < 8; ++j) {
                int c4 = q * 32 + j * 4;
                float4 v = *(const float4*)(arow + c4);
                if (NORM && p == 0) {
                    float4 m  = *(const float4*)(nm + c4);
                    float4 iv = *(const float4*)(nm + 2048 + c4);
                    v.x = (v.x - m.x) * iv.x;
                    v.y = (v.y - m.y) * iv.y;
                    v.z = (v.z - m.z) * iv.z;
                    v.w = (v.w - m.w) * iv.w;
                }
                uint2 hv, lv;
                split4(v, hv, lv);
                uint32_t off = r256 + ((((c4 >> 3) ^ r7) << 4) | ((c4 & 7) << 1));
                *(uint2*)(tiles + off) = hv;
                *(uint2*)(tiles + 32768 + off) = lv;
            }
        }
        // copy W phase chunk (64KB)
        {
            const float4* wsrc = (const float4*)(Wt + (size_t)p * 65536);
            float4* wdst = (float4*)(tiles + 65536);
#pragma unroll
            for (int j = 0; j < 8; ++j)
                wdst[tid + j * 512] = wsrc[tid + j * 512];
        }
        __syncthreads();

#pragma unroll
        for (int ks = 0; ks < 8; ++ks) {
            const int kb = ks * 2;
            uint32_t ahi[2][4], alo[2][4], bhi[2][4], blo[2][4];
#pragma unroll
            for (int mt = 0; mt < 2; ++mt) {
                uint32_t sw = (uint32_t)(((kb + akq) ^ ar7[mt]) << 4);
                ldmx4(ahi[mt], tiles_u32 + arow256[mt] + sw);
                ldmx4(alo[mt], tiles_u32 + 32768 + arow256[mt] + sw);
            }
#pragma unroll
            for (int pj = 0; pj < 2; ++pj) {
                uint32_t swb = (uint32_t)(((kb + bkq) ^ br7[pj]) << 4);
                ldmx4(bhi[pj], tiles_u32 + 65536 + brow256[pj] + swb);
                ldmx4(blo[pj], tiles_u32 + 98304 + brow256[pj] + swb);
            }
#pragma unroll
            for (int mt = 0; mt < 2; ++mt)
#pragma unroll
                for (int nt = 0; nt < 4; ++nt) {
                    const uint32_t* bh = &bhi[nt >> 1][(nt & 1) * 2];
                    const uint32_t* bl = &blo[nt >> 1][(nt & 1) * 2];
                    mma16816(c[mt][nt], ahi[mt], bh);
                    mma16816(c[mt][nt], ahi[mt], bl);
                    mma16816(c[mt][nt], alo[mt], bh);
                }
        }
    }

    const int gr = lid >> 2;
    const int gc = (lid & 3) << 1;
#pragma unroll
    for (int mt = 0; mt < 2; ++mt) {
        int mrow = m0 + warp_m * 32 + mt * 16 + gr;
#pragma unroll
        for (int nt = 0; nt < 4; ++nt) {
            int n = warp_n * 32 + nt * 8 + gc;
            float2 pb = *(const float2*)(postBias + n);
            *(float2*)(C + (size_t)mrow * 128 + n) =
                make_float2(fmaxf(c[mt][nt][0] + pb.x, 0.f), fmaxf(c[mt][nt][1] + pb.y, 0.f));
            *(float2*)(C + (size_t)(mrow + 8) * 128 + n) =
                make_float2(fmaxf(c[mt][nt][2] + pb.x, 0.f), fmaxf(c[mt][nt][3] + pb.y, 0.f));
        }
    }
}

// ---------------- misc kernels ----------------
__global__ void zero_kernel(float4* __restrict__ p, int n4) {
    int i = blockIdx.x * blockDim.x + threadIdx.x;
    if (i < n4) p[i] = make_float4(0.f, 0.f, 0.f, 0.f);
}

__global__ void encoder_kernel(const float* __restrict__ X,
                               const float* __restrict__ W,
                               const float* __restrict__ B,
                               float* __restrict__ H) {
    int idx = blockIdx.x * blockDim.x + threadIdx.x;
    int n = idx >> 7;
    int c = idx & 127;
    float4 xv = ((const float4*)X)[n];
    float v = B[c];
    v += xv.x * W[c];
    v += xv.y * W[128 + c];
    v += xv.z * W[256 + c];
    v += xv.w * W[384 + c];
    H[idx] = v;
}

__global__ void norm_stats_kernel(const float* __restrict__ U) {
    int b = blockIdx.x;
    int ch = blockIdx.y;
    int c = threadIdx.x;
    int n0 = b * NSAMPLES + ch * 128;
    float s = 0.f, qq = 0.f;
#pragma unroll 4
    for (int i = 0; i < 128; ++i) {
        float v = U[(size_t)(n0 + i) * 128 + c];
        s += v;
        qq += v * v;
    }
    atomicAdd(&g_nstats[b * 128 + c], s);
    atomicAdd(&g_nstats[NBATCH * NHID + b * 128 + c], qq);
}

__global__ void norm_final_kernel() {
    int idx = blockIdx.x * 256 + threadIdx.x;
    if (idx < NBATCH * NHID) {
        float s = g_nstats[idx];
        float q = g_nstats[NBATCH * NHID + idx];
        float mean = s * (1.0f / NSAMPLES);
        float var = q * (1.0f / NSAMPLES) - mean * mean;
        g_nstats[idx] = mean;
        g_nstats[NBATCH * NHID + idx] = rsqrtf(var + EPSV);
    }
}

__global__ void decoder_kernel(const float* __restrict__ H,
                               const float* __restrict__ nstats,
                               const float* __restrict__ W,
                               const float* __restrict__ B,
                               float* __restrict__ GX,
                               float* __restrict__ x_out) {
    int gthread = blockIdx.x * blockDim.x + threadIdx.x;
    int n = gthread >> 5;
    int lane = threadIdx.x & 31;
    if (n >= N_NODES) return;
    const float* hr = H + (size_t)n * 128;
    const float* nm = nstats + (n >> 10) * 128;
    float a0 = 0.f, a1 = 0.f, a2 = 0.f, a3 = 0.f;
#pragma unroll
    for (int k = 0; k < 128; k += 32) {
        float hv = (hr[k + lane] - nm[k + lane]) * nm[2048 + k + lane];
        float4 w = ((const float4*)W)[k + lane];
        a0 += hv * w.x;
        a1 += hv * w.y;
        a2 += hv * w.z;
        a3 += hv * w.w;
    }
#pragma unroll
    for (int off = 16; off > 0; off >>= 1) {
        a0 += __shfl_xor_sync(0xFFFFFFFFu, a0, off);
        a1 += __shfl_xor_sync(0xFFFFFFFFu, a1, off);
        a2 += __shfl_xor_sync(0xFFFFFFFFu, a2, off);
        a3 += __shfl_xor_sync(0xFFFFFFFFu, a3, off);
    }
    if (lane == 0) {
        float z0 = 1.f / (1.f + expf(-(a0 + B[0])));
        float z1 = 1.f / (1.f + expf(-(a1 + B[1])));
        float z2 = 1.f / (1.f + expf(-(a2 + B[2])));
        float z3 = 1.f / (1.f + expf(-(a3 + B[3])));
        ((float4*)GX)[n] = make_float4(z0, z1, z2, z3);
        if (x_out) {
            x_out[n * 4 + 0] = z0;
            x_out[n * 4 + 1] = z1;
            x_out[n * 4 + 2] = z2;
            x_out[n * 4 + 3] = z3;
        }
    }
}

__global__ void disc_kernel(const float* __restrict__ GX) {
    __shared__ float4 sx[NSAMPLES];
    __shared__ float red1[128];
    __shared__ float red2[128];
    int b = blockIdx.x;
    int chunk = blockIdx.y;
    int tid = threadIdx.x;
    const float4* xb = (const float4*)GX + (size_t)b * NSAMPLES;
    for (int i = tid; i < NSAMPLES; i += 128) sx[i] = xb[i];
    __syncthreads();
    int i = chunk * 128 + tid;
    float4 xi = sx[i];
    float p1 = (1.f - xi.x * xi.x) * (1.f - xi.y * xi.y) *
               (1.f - xi.z * xi.z) * (1.f - xi.w * xi.w);
    float s2 = 0.f;
#pragma unroll 4
    for (int j = 0; j < NSAMPLES; ++j) {
        float4 xj = sx[j];
        float t = (1.f - fmaxf(xi.x, xj.x)) * (1.f - fmaxf(xi.y, xj.y)) *
                  (1.f - fmaxf(xi.z, xj.z)) * (1.f - fmaxf(xi.w, xj.w));
        s2 += t;
    }
    red1[tid] = p1;
    red2[tid] = s2;
    __syncthreads();
    for (int s = 64; s > 0; s >>= 1) {
        if (tid < s) {
            red1[tid] += red1[tid + s];
            red2[tid] += red2[tid + s];
        }
        __syncthreads();
    }
    if (tid == 0) {
        atomicAdd(&g_dsum[b], red1[0]);
        atomicAdd(&g_dsum[16 + b], red2[0]);
    }
}

__global__ void final_kernel(float* __restrict__ loss_out) {
    if (threadIdx.x == 0 && blockIdx.x == 0) {
        float acc = 0.f;
        const float invN = 1.0f / (float)NSAMPLES;
        for (int b = 0; b < NBATCH; ++b) {
            float s1 = g_dsum[b];
            float s2 = g_dsum[16 + b];
            float v = (1.0f / 81.0f) - invN * 0.125f * s1 + s2 * invN * invN;
            acc += sqrtf(v);
        }
        float loss = acc / (float)NBATCH;
        if (loss_out) *loss_out = loss;
    }
}

// ---------------- launch ----------------
extern "C" void kernel_launch(void* const* d_in, const int* in_sizes, int n_in,
                              void* d_out, int out_size) {
    const float *X, *enc_w, *enc_b, *dec_w, *dec_b;
    const float *m1w, *m1b, *m2w, *m2b, *u1w, *u1b, *u2w, *u2b;
    const int* ei = (const int*)d_in[1];
    X = (const float*)d_in[0];
    bool dictOrder = (in_sizes[5] == 512);
    if (dictOrder) {
        enc_w = (const float*)d_in[3];  enc_b = (const float*)d_in[4];
        dec_w = (const float*)d_in[5];  dec_b = (const float*)d_in[6];
        m1w = (const float*)d_in[7];    m1b = (const float*)d_in[8];
        m2w = (const float*)d_in[9];    m2b = (const float*)d_in[10];
        u1w = (const float*)d_in[11];   u1b = (const float*)d_in[12];
        u2w = (const float*)d_in[13];   u2b = (const float*)d_in[14];
    } else {
        enc_w = (const float*)d_in[3];  enc_b = (const float*)d_in[4];
        m1w = (const float*)d_in[5];    m1b = (const float*)d_in[6];
        m2w = (const float*)d_in[7];    m2b = (const float*)d_in[8];
        u1w = (const float*)d_in[9];    u1b = (const float*)d_in[10];
        u2w = (const float*)d_in[11];   u2b = (const float*)d_in[12];
        dec_w = (const float*)d_in[13]; dec_b = (const float*)d_in[14];
    }
    const int* src = ei;
    const int* dst = ei + N_EDGES;

    void* p;
    float *h_, *Pd, *Ps, *agg, *t1, *t2, *gx, *nst, *dsum;
    char* wt;
    cudaGetSymbolAddress(&p, g_h);      h_  = (float*)p;
    cudaGetSymbolAddress(&p, g_Pd);     Pd  = (float*)p;
    cudaGetSymbolAddress(&p, g_Ps);     Ps  = (float*)p;
    cudaGetSymbolAddress(&p, g_agg);    agg = (float*)p;
    cudaGetSymbolAddress(&p, g_t1);     t1  = (float*)p;
    cudaGetSymbolAddress(&p, g_t2);     t2  = (float*)p;
    cudaGetSymbolAddress(&p, g_x);      gx  = (float*)p;
    cudaGetSymbolAddress(&p, g_nstats); nst = (float*)p;
    cudaGetSymbolAddress(&p, g_dsum);   dsum = (float*)p;
    cudaGetSymbolAddress(&p, g_wt);     wt  = (char*)p;

    float* out = (float*)d_out;
    float* loss_out;
    float* x_out;
    if (out_size >= N_NODES * DIMX + 1) { loss_out = out; x_out = out + 1; }
    else if (out_size == N_NODES * DIMX) { loss_out = nullptr; x_out = out; }
    else { loss_out = out; x_out = nullptr; }

    cudaFuncSetAttribute(tc_node<1,0,0>, cudaFuncAttributeMaxDynamicSharedMemorySize, NODE_SMEM);
    cudaFuncSetAttribute(tc_node<1,0,1>, cudaFuncAttributeMaxDynamicSharedMemorySize, NODE_SMEM);
    cudaFuncSetAttribute(tc_node<0,1,0>, cudaFuncAttributeMaxDynamicSharedMemorySize, NODE_SMEM);
    cudaFuncSetAttribute(tc_edge,        cudaFuncAttributeMaxDynamicSharedMemorySize, EDGE_SMEM);
    cudaFuncSetAttribute(tc_u1<0>,       cudaFuncAttributeMaxDynamicSharedMemorySize, U1_SMEM);
    cudaFuncSetAttribute(tc_u1<1>,       cudaFuncAttributeMaxDynamicSharedMemorySize, U1_SMEM);

    // ---- weight prep ----
    PrepJobs jobs;
    for (int l = 0; l < NLAYERS; ++l) {
        char* lb = wt + (size_t)l * WT_LAYER_STRIDE;
        jobs.src[l*5+0] = m1w + (size_t)l * 256 * 128;            jobs.dst[l*5+0] = lb + WT_W1A; jobs.nelem[l*5+0] = 128*128;
        jobs.src[l*5+1] = m1w + (size_t)l * 256 * 128 + 128*128;  jobs.dst[l*5+1] = lb + WT_W1B; jobs.nelem[l*5+1] = 128*128;
        jobs.src[l*5+2] = m2w + (size_t)l * 128 * 128;            jobs.dst[l*5+2] = lb + WT_W2;  jobs.nelem[l*5+2] = 128*128;
        jobs.src[l*5+3] = u1w + (size_t)l * 256 * 128;            jobs.dst[l*5+3] = lb + WT_U1;  jobs.nelem[l*5+3] = 256*128;
        jobs.src[l*5+4] = u2w + (size_t)l * 128 * 128;            jobs.dst[l*5+4] = lb + WT_U2;  jobs.nelem[l*5+4] = 128*128;
    }
    prep_w_all<<<dim3(128, 15), 256>>>(jobs);

    encoder_kernel<<<(N_NODES * NHID) / 256, 256>>>(X, enc_w, enc_b, h_);

    for (int l = 0; l < NLAYERS; ++l) {
        char* lb = wt + (size_t)l * WT_LAYER_STRIDE;
        const float* B1  = m1b + l * 128;
        const float* B2  = m2b + l * 128;
        const float* BU1 = u1b + l * 128;
        const float* BU2 = u2b + l * 128;
        const float* Aprev = (l == 0) ? h_ : t2;

        if (l == 0)
            tc_node<1,0,0><<<512, 256, NODE_SMEM>>>(Aprev, lb + WT_W1A, nullptr, Pd, Ps, nullptr);
        else
            tc_node<1,0,1><<<512, 256, NODE_SMEM>>>(Aprev, lb + WT_W1A, nullptr, Pd, Ps, nst);

        zero_kernel<<<(N_NODES * NHID / 4) / 256, 256>>>((float4*)agg, N_NODES * NHID / 4);
        tc_edge<<<148, 512, EDGE_SMEM>>>(Pd, Ps, lb + WT_W2, B1, B2, agg, dst, src);

        if (l == 0)
            tc_u1<0><<<128, 512, U1_SMEM>>>(Aprev, agg, lb + WT_U1, BU1, t1, nullptr);
        else
            tc_u1<1><<<128, 512, U1_SMEM>>>(Aprev, agg, lb + WT_U1, BU1, t1, nst);

        tc_node<0,1,0><<<256, 256, NODE_SMEM>>>(t1, lb + WT_U2, BU2, t2, nullptr, nullptr);

        zero_kernel<<<4, 256>>>((float4*)nst, (2 * NBATCH * NHID) / 4);
        norm_stats_kernel<<<dim3(NBATCH, 8), 128>>>(t2);
        norm_final_kernel<<<8, 256>>>();
    }

    decoder_kernel<<<(N_NODES * 32) / 256, 256>>>(t2, nst, dec_w, dec_b, gx, x_out);
    zero_kernel<<<1, 256>>>((float4*)dsum, 8);
    disc_kernel<<<dim3(NBATCH, 8), 128>>>(gx);
    final_kernel<<<1, 1>>>(loss_out);
}